// round 15
// baseline (speedup 1.0000x reference)
#include <cuda_runtime.h>

// GaussianEdgeGuide — prep kernel + smem-free, halo-free full-width stencil.
//
// Algebra: softmax over the 9 neighborhood positions of
//   -theta*(edge_center + edge_neighbor - max_edge)
// has edge_center and max_edge constant along the softmax axis, so
//   weight_k(q) = E(q+d_k) / S(q),   E(x) = exp(-theta*edge(x)) (E=1 outside),
//   S(q) = sum_k E(q+d_k).
// One iteration: mask'(q) = box3(mask*E)(q) / S(q)   (mask zero-padded).
// iter1 = box3(mask*E) * W*E,  out = box3(iter1) * W.
//
// Stencil (R12 layout): warp spans the full 256-px row, lane l owns 4-px
// groups at x=4l and x=128+4l (contiguous LDG.128s); borders are zero
// shuffle-ins, the 127<->128 seam is two warp broadcasts. No smem, no halo.
//
// Changes vs R12 (which plateaued at ~32.6us, latency-structure bound):
//  1. IE stream removed: E(a) kept one iteration in rolling registers,
//     W(a) loaded once and rolled for the output row (W(r)=W(a-1)).
//     Loads/row-iter: 8 -> 6 LDG.128 (-25%); +8 FMUL/row (fma pipe idle).
//  2. Pairwise-sum rolling: keep (row[i-1]+row[i], row[i]) instead of three
//     raw rows for both P and M verticals: v = u + new; u' = last + new.
//     Bit-identical association, -16 floats of persistent state, so the
//     64-reg cap (16 CTAs/SM, 1.03 waves) spills less than R12.

#define NB   8
#define NC   19
#define HW   256
#define NPIX (HW * HW)

__device__ __align__(16) float g_E[NB * NPIX];   // exp(-40*edge)
__device__ __align__(16) float g_W[NB * NPIX];   // 1 / box3(E)

// ---------------------------------------------------------------------------
// Kernel 1: per-pixel E and W (32x32 tiles).
// ---------------------------------------------------------------------------
__global__ __launch_bounds__(256, 4)
void geg_prep(const float* __restrict__ edge)
{
    __shared__ float sE[34 * 35];   // 34x34 E with halo 1, E=1 outside image

    const int tid = threadIdx.x;
    const int h0 = blockIdx.y * 32, w0 = blockIdx.x * 32;
    const int n  = blockIdx.z;
    const float* eimg = edge + (n << 16);

    for (int idx = tid; idx < 34 * 34; idx += 256) {
        int i = idx / 34, j = idx - i * 34;
        int gy = h0 - 1 + i, gx = w0 - 1 + j;
        float e = 1.0f;  // exp(-40 * 0) at zero-padded border
        if ((unsigned)gy < 256u && (unsigned)gx < 256u)
            e = __expf(-40.0f * eimg[(gy << 8) + gx]);
        sE[i * 35 + j] = e;
    }
    __syncthreads();

    const int tj = tid & 31, tb = tid >> 5;
    #pragma unroll
    for (int k = 0; k < 4; ++k) {
        int ti = tb + 8 * k;
        const float* p = &sE[ti * 35 + tj];
        float s = p[0]  + p[1]  + p[2]
                + p[35] + p[36] + p[37]
                + p[70] + p[71] + p[72];
        int g = (n << 16) + ((h0 + ti) << 8) + (w0 + tj);
        g_E[g] = p[36];
        g_W[g] = __fdividef(1.0f, s);
    }
}

// ---------------------------------------------------------------------------
// Kernel 2: stencil. Grid (16, NB*NC), block 64 (2 warps).
// Warp owns 8 output rows of the full 256-px width.
// ---------------------------------------------------------------------------
__global__ __launch_bounds__(64, 16)
void geg_stencil(const float* __restrict__ mask,
                 float* __restrict__ out)
{
    const unsigned FULL = 0xffffffffu;
    const int lane = threadIdx.x & 31;
    const int warp = threadIdx.x >> 5;     // 0..1
    const int z    = blockIdx.y;           // n * NC + c
    const int n    = z / NC;

    const float4* mch = (const float4*)(mask + ((size_t)z << 16));
    float4*       och = (float4*)(out  + ((size_t)z << 16));
    const float4* Eb  = (const float4*)(g_E + (n << 16));
    const float4* Wb  = (const float4*)(g_W + (n << 16));

    const int qa = lane;        // f4 col of g0 (px 4*lane)
    const int qb = 32 + lane;   // f4 col of g1 (px 128 + 4*lane)

    const int R0 = (blockIdx.x << 4) + (warp << 3);  // first output row

    const float4 Z = make_float4(0.f, 0.f, 0.f, 0.f);

    // rolling state (pairwise-sum form):
    //   puA/puB = P(a-2)+P(a-1), plA/plB = P(a-1)
    //   muA/muB = M(a-2)+M(a-1), mlA/mlB = M(a-1)
    //   eA/eB   = E(a)    (for the iter1 multiply)
    //   wpA/wpB = W(a-1)  (for the output multiply)
    float4 puA, puB, plA, plB, muA, muB, mlA, mlB, eA, eB, wpA, wpB;

    // prologue: P rows R0-2, R0-1 (zero above the image); E of row R0-1
    {
        float4 x0A = Z, x0B = Z, x1A = Z, x1B = Z;
        int gy = R0 - 2;
        if ((unsigned)gy < 256u) {
            float4 m = mch[(gy << 6) + qa], e = Eb[(gy << 6) + qa];
            x0A = make_float4(m.x*e.x, m.y*e.y, m.z*e.z, m.w*e.w);
            m = mch[(gy << 6) + qb]; e = Eb[(gy << 6) + qb];
            x0B = make_float4(m.x*e.x, m.y*e.y, m.z*e.z, m.w*e.w);
        }
        gy = R0 - 1;
        eA = Z; eB = Z;
        if ((unsigned)gy < 256u) {
            float4 m = mch[(gy << 6) + qa], e = Eb[(gy << 6) + qa];
            x1A = make_float4(m.x*e.x, m.y*e.y, m.z*e.z, m.w*e.w);
            eA = e;
            m = mch[(gy << 6) + qb]; e = Eb[(gy << 6) + qb];
            x1B = make_float4(m.x*e.x, m.y*e.y, m.z*e.z, m.w*e.w);
            eB = e;
        }
        // pu = P(R0-2)+P(R0-1), pl = P(R0-1): keep (x0+x1) association
        puA = make_float4(x0A.x + x1A.x, x0A.y + x1A.y,
                          x0A.z + x1A.z, x0A.w + x1A.w);
        puB = make_float4(x0B.x + x1B.x, x0B.y + x1B.y,
                          x0B.z + x1B.z, x0B.w + x1B.w);
        plA = x1A; plB = x1B;
    }
    muA = muB = mlA = mlB = Z;
    wpA = wpB = Z;   // first use overwritten before read (a=R0 iter sets it)

    #pragma unroll
    for (int a = R0 - 1; a <= R0 + 8; ++a) {   // iter1 row a
        // load P row a+1 (and its E for next iteration's multiply)
        float4 pA2 = Z, pB2 = Z, eA2 = Z, eB2 = Z;
        int gy = a + 1;
        if ((unsigned)gy < 256u) {
            float4 m = mch[(gy << 6) + qa];
            eA2 = Eb[(gy << 6) + qa];
            pA2 = make_float4(m.x*eA2.x, m.y*eA2.y, m.z*eA2.z, m.w*eA2.w);
            m = mch[(gy << 6) + qb];
            eB2 = Eb[(gy << 6) + qb];
            pB2 = make_float4(m.x*eB2.x, m.y*eB2.y, m.z*eB2.z, m.w*eB2.w);
        }

        const bool arow = (unsigned)a < 256u;
        float4 wA, wB;
        if (arow) { wA = Wb[(a << 6) + qa]; wB = Wb[(a << 6) + qb]; }

        // vertical 3-sums at row a: v = pu + p_new  (== (P0+P1)+P2)
        float c1 = puA.x + pA2.x;
        float c2 = puA.y + pA2.y;
        float c3 = puA.z + pA2.z;
        float c4 = puA.w + pA2.w;
        float d1 = puB.x + pB2.x;
        float d2 = puB.y + pB2.y;
        float d3 = puB.z + pB2.z;
        float d4 = puB.w + pB2.w;

        // horizontal exchange: neighbors + the 127<->128 seam broadcasts
        float l0 = __shfl_up_sync  (FULL, c4, 1);
        float r0 = __shfl_down_sync(FULL, c1, 1);
        float l1 = __shfl_up_sync  (FULL, d4, 1);
        float r1 = __shfl_down_sync(FULL, d1, 1);
        float s0 = __shfl_sync(FULL, c4, 31);  // px 127 sum
        float s1 = __shfl_sync(FULL, d1, 0);   // px 128 sum
        if (lane == 0)  { l0 = 0.f; l1 = s0; } // px -1 -> zero-pad
        if (lane == 31) { r0 = s1; r1 = 0.f; } // px 256 -> zero-pad

        // iter1 row a: mrow = hsum * (W(a)*E(a))  (zero outside image)
        float4 mrow = Z, urow = Z;
        if (arow) {
            float4 ieA = make_float4(wA.x*eA.x, wA.y*eA.y,
                                     wA.z*eA.z, wA.w*eA.w);
            float4 ieB = make_float4(wB.x*eB.x, wB.y*eB.y,
                                     wB.z*eB.z, wB.w*eB.w);
            mrow.x = (l0 + c1 + c2) * ieA.x;
            mrow.y = (c1 + c2 + c3) * ieA.y;
            mrow.z = (c2 + c3 + c4) * ieA.z;
            mrow.w = (c3 + c4 + r0) * ieA.w;
            urow.x = (l1 + d1 + d2) * ieB.x;
            urow.y = (d1 + d2 + d3) * ieB.y;
            urow.z = (d2 + d3 + d4) * ieB.z;
            urow.w = (d3 + d4 + r1) * ieB.w;
        }

        if (a >= R0 + 1) {
            int r = a - 1;                    // output row, in [0,255]
            // v = mu + mrow  (== (M0+M1)+M2)
            float v1 = muA.x + mrow.x;
            float v2 = muA.y + mrow.y;
            float v3 = muA.z + mrow.z;
            float v4 = muA.w + mrow.w;
            float w1 = muB.x + urow.x;
            float w2 = muB.y + urow.y;
            float w3 = muB.z + urow.z;
            float w4 = muB.w + urow.w;

            float L0 = __shfl_up_sync  (FULL, v4, 1);
            float Rr0 = __shfl_down_sync(FULL, v1, 1);
            float L1 = __shfl_up_sync  (FULL, w4, 1);
            float Rr1 = __shfl_down_sync(FULL, w1, 1);
            float S0 = __shfl_sync(FULL, v4, 31);
            float S1 = __shfl_sync(FULL, w1, 0);
            if (lane == 0)  { L0 = 0.f; L1 = S0; }
            if (lane == 31) { Rr0 = S1; Rr1 = 0.f; }

            float4 o;
            o.x = (L0 + v1 + v2) * wpA.x;
            o.y = (v1 + v2 + v3) * wpA.y;
            o.z = (v2 + v3 + v4) * wpA.z;
            o.w = (v3 + v4 + Rr0) * wpA.w;
            och[(r << 6) + qa] = o;

            o.x = (L1 + w1 + w2) * wpB.x;
            o.y = (w1 + w2 + w3) * wpB.y;
            o.z = (w2 + w3 + w4) * wpB.z;
            o.w = (w3 + w4 + Rr1) * wpB.w;
            och[(r << 6) + qb] = o;
        }

        // roll the pairwise sums: u' = last + new; last' = new
        muA = make_float4(mlA.x + mrow.x, mlA.y + mrow.y,
                          mlA.z + mrow.z, mlA.w + mrow.w);
        muB = make_float4(mlB.x + urow.x, mlB.y + urow.y,
                          mlB.z + urow.z, mlB.w + urow.w);
        mlA = mrow; mlB = urow;
        puA = make_float4(plA.x + pA2.x, plA.y + pA2.y,
                          plA.z + pA2.z, plA.w + pA2.w);
        puB = make_float4(plB.x + pB2.x, plB.y + pB2.y,
                          plB.z + pB2.z, plB.w + pB2.w);
        plA = pA2; plB = pB2;
        eA = eA2; eB = eB2;
        if (arow) { wpA = wA; wpB = wB; }   // W(r) for the next output row
    }
}

extern "C" void kernel_launch(void* const* d_in, const int* in_sizes, int n_in,
                              void* d_out, int out_size)
{
    const float* mask = (const float*)d_in[0];
    const float* edge = (const float*)d_in[1];
    // d_in[2] = iter_n is fixed at 2 by the problem setup; 2 iterations fused.
    (void)in_sizes; (void)n_in; (void)out_size;

    dim3 gp(HW / 32, HW / 32, NB);            // 8 x 8 x 8
    geg_prep<<<gp, 256>>>(edge);

    dim3 gs(HW / 16, NB * NC);                // 16 x 152 = 2432 CTAs
    geg_stencil<<<gs, 64>>>(mask, (float*)d_out);
}

// round 17
// speedup vs baseline: 1.4544x; 1.4544x over previous
#include <cuda_runtime.h>

// GaussianEdgeGuide — prep kernel + smem-free, halo-free full-width stencil.
//
// Algebra: softmax over the 9 neighborhood positions of
//   -theta*(edge_center + edge_neighbor - max_edge)
// has edge_center and max_edge constant along the softmax axis, so
//   weight_k(q) = E(q+d_k) / S(q),   E(x) = exp(-theta*edge(x)) (E=1 outside),
//   S(q) = sum_k E(q+d_k).
// One iteration: mask'(q) = box3(mask*E)(q) / S(q)   (mask zero-padded).
// iter1 = box3(mask*E) * IE  (IE = W*E),  out = box3(iter1) * W.
//
// Stencil = R12 dataflow (best measured: 32.6us): warp spans the full 256-px
// row, lane l owns 4-px groups at x=4l and x=128+4l; borders are zero
// shuffle-ins, the 127<->128 seam is two warp broadcasts. E/IE/W streams
// from prep; 3-row register rolling; no smem; 64-reg cap = 32 warps/SM,
// single wave.
//
// Change vs R12: all elementwise math as f32x2 packed ops (add.rn.f32x2 /
// mul.rn.f32x2) on (x,y)/(z,w) 64-bit pairs. ~27% fewer FMA-pipe slots per
// row-iter, zero extra registers, bit-identical association (R15 showed
// trading loads for carried state loses; this trades nothing).

#define NB   8
#define NC   19
#define HW   256
#define NPIX (HW * HW)

typedef unsigned long long u64;

__device__ __align__(16) float g_E [NB * NPIX];   // exp(-40*edge)
__device__ __align__(16) float g_W [NB * NPIX];   // 1 / box3(E)
__device__ __align__(16) float g_IE[NB * NPIX];   // W * E

__device__ __forceinline__ u64 pk(float lo, float hi)
{
    u64 r;
    asm("mov.b64 %0, {%1, %2};" : "=l"(r) : "f"(lo), "f"(hi));
    return r;
}
__device__ __forceinline__ void upk(float& lo, float& hi, u64 v)
{
    asm("mov.b64 {%0, %1}, %2;" : "=f"(lo), "=f"(hi) : "l"(v));
}
__device__ __forceinline__ u64 padd(u64 a, u64 b)
{
    u64 r;
    asm("add.rn.f32x2 %0, %1, %2;" : "=l"(r) : "l"(a), "l"(b));
    return r;
}
__device__ __forceinline__ u64 pmul(u64 a, u64 b)
{
    u64 r;
    asm("mul.rn.f32x2 %0, %1, %2;" : "=l"(r) : "l"(a), "l"(b));
    return r;
}

// ---------------------------------------------------------------------------
// Kernel 1: per-pixel E, W, IE (32x32 tiles; unchanged from R12).
// ---------------------------------------------------------------------------
__global__ __launch_bounds__(256, 4)
void geg_prep(const float* __restrict__ edge)
{
    __shared__ float sE[34 * 35];   // 34x34 E with halo 1, E=1 outside image

    const int tid = threadIdx.x;
    const int h0 = blockIdx.y * 32, w0 = blockIdx.x * 32;
    const int n  = blockIdx.z;
    const float* eimg = edge + (n << 16);

    for (int idx = tid; idx < 34 * 34; idx += 256) {
        int i = idx / 34, j = idx - i * 34;
        int gy = h0 - 1 + i, gx = w0 - 1 + j;
        float e = 1.0f;  // exp(-40 * 0) at zero-padded border
        if ((unsigned)gy < 256u && (unsigned)gx < 256u)
            e = __expf(-40.0f * eimg[(gy << 8) + gx]);
        sE[i * 35 + j] = e;
    }
    __syncthreads();

    const int tj = tid & 31, tb = tid >> 5;
    #pragma unroll
    for (int k = 0; k < 4; ++k) {
        int ti = tb + 8 * k;
        const float* p = &sE[ti * 35 + tj];
        float s = p[0]  + p[1]  + p[2]
                + p[35] + p[36] + p[37]
                + p[70] + p[71] + p[72];
        float w  = __fdividef(1.0f, s);
        float ec = p[36];
        int g = (n << 16) + ((h0 + ti) << 8) + (w0 + tj);
        g_E [g] = ec;
        g_W [g] = w;
        g_IE[g] = w * ec;
    }
}

// ---------------------------------------------------------------------------
// Kernel 2: stencil. Grid (16, NB*NC), block 64 (2 warps).
// Warp owns 8 output rows of the full 256-px width.
// ---------------------------------------------------------------------------
__global__ __launch_bounds__(64, 16)
void geg_stencil(const float* __restrict__ mask,
                 float* __restrict__ out)
{
    const unsigned FULL = 0xffffffffu;
    const int lane = threadIdx.x & 31;
    const int warp = threadIdx.x >> 5;     // 0..1
    const int z    = blockIdx.y;           // n * NC + c
    const int n    = z / NC;

    const ulonglong2* mch = (const ulonglong2*)(mask + ((size_t)z << 16));
    ulonglong2*       och = (ulonglong2*)(out  + ((size_t)z << 16));
    const ulonglong2* Eb  = (const ulonglong2*)(g_E  + (n << 16));
    const ulonglong2* IEb = (const ulonglong2*)(g_IE + (n << 16));
    const ulonglong2* Wb  = (const ulonglong2*)(g_W  + (n << 16));

    const int qa = lane;        // f4 col of g0 (px 4*lane)
    const int qb = 32 + lane;   // f4 col of g1 (px 128 + 4*lane)

    const int R0 = (blockIdx.x << 4) + (warp << 3);  // first output row

    const ulonglong2 Z2 = make_ulonglong2(0ull, 0ull);   // two packed +0.0f

    // rolling state: P rows (mask*E) a-2, a-1 and M rows a-2, a-1, packed
    ulonglong2 pa0, pa1, pb0, pb1;
    ulonglong2 ma0, ma1, mb0, mb1;

    // prologue: P rows R0-2, R0-1 (zero when above the image)
    {
        int gy = R0 - 2;
        if ((unsigned)gy < 256u) {
            ulonglong2 m = mch[(gy << 6) + qa], e = Eb[(gy << 6) + qa];
            pa0.x = pmul(m.x, e.x); pa0.y = pmul(m.y, e.y);
            m = mch[(gy << 6) + qb]; e = Eb[(gy << 6) + qb];
            pb0.x = pmul(m.x, e.x); pb0.y = pmul(m.y, e.y);
        } else { pa0 = Z2; pb0 = Z2; }
        gy = R0 - 1;
        if ((unsigned)gy < 256u) {
            ulonglong2 m = mch[(gy << 6) + qa], e = Eb[(gy << 6) + qa];
            pa1.x = pmul(m.x, e.x); pa1.y = pmul(m.y, e.y);
            m = mch[(gy << 6) + qb]; e = Eb[(gy << 6) + qb];
            pb1.x = pmul(m.x, e.x); pb1.y = pmul(m.y, e.y);
        } else { pa1 = Z2; pb1 = Z2; }
    }
    ma0 = ma1 = mb0 = mb1 = Z2;

    #pragma unroll
    for (int a = R0 - 1; a <= R0 + 8; ++a) {   // iter1 row a
        // load P row a+1
        ulonglong2 pa2, pb2;
        int gy = a + 1;
        if ((unsigned)gy < 256u) {
            ulonglong2 m = mch[(gy << 6) + qa], e = Eb[(gy << 6) + qa];
            pa2.x = pmul(m.x, e.x); pa2.y = pmul(m.y, e.y);
            m = mch[(gy << 6) + qb]; e = Eb[(gy << 6) + qb];
            pb2.x = pmul(m.x, e.x); pb2.y = pmul(m.y, e.y);
        } else { pa2 = Z2; pb2 = Z2; }

        // vertical 3-sums at row a (packed, (p0+p1)+p2 association)
        u64 cLo = padd(padd(pa0.x, pa1.x), pa2.x);
        u64 cHi = padd(padd(pa0.y, pa1.y), pa2.y);
        u64 dLo = padd(padd(pb0.x, pb1.x), pb2.x);
        u64 dHi = padd(padd(pb0.y, pb1.y), pb2.y);

        float c1, c2, c3, c4, d1, d2, d3, d4;
        upk(c1, c2, cLo); upk(c3, c4, cHi);
        upk(d1, d2, dLo); upk(d3, d4, dHi);

        // horizontal exchange: neighbors + the 127<->128 seam broadcasts
        float l0 = __shfl_up_sync  (FULL, c4, 1);
        float r0 = __shfl_down_sync(FULL, c1, 1);
        float l1 = __shfl_up_sync  (FULL, d4, 1);
        float r1 = __shfl_down_sync(FULL, d1, 1);
        float s0 = __shfl_sync(FULL, c4, 31);  // px 127 sum
        float s1 = __shfl_sync(FULL, d1, 0);   // px 128 sum
        if (lane == 0)  { l0 = 0.f; l1 = s0; } // px -1 -> zero-pad
        if (lane == 31) { r0 = s1; r1 = 0.f; } // px 256 -> zero-pad

        // iter1 row a: mrow = hsum * IE (zero outside image)
        // packed hsum keeps R12's left association:
        //   (pk(l,c1)+cLo)+pk(c2,c3) = ((l+c1)+c2, (c1+c2)+c3)
        //   (pk(c2,c3)+cHi)+pk(c4,r) = ((c2+c3)+c4, (c3+c4)+r)
        ulonglong2 mrA, mrB;
        const bool arow = (unsigned)a < 256u;
        if (arow) {
            ulonglong2 ieA = IEb[(a << 6) + qa], ieB = IEb[(a << 6) + qb];
            u64 c23 = pk(c2, c3);
            mrA.x = pmul(padd(padd(pk(l0, c1), cLo), c23), ieA.x);
            mrA.y = pmul(padd(padd(c23, cHi), pk(c4, r0)), ieA.y);
            u64 d23 = pk(d2, d3);
            mrB.x = pmul(padd(padd(pk(l1, d1), dLo), d23), ieB.x);
            mrB.y = pmul(padd(padd(d23, dHi), pk(d4, r1)), ieB.y);
        } else { mrA = Z2; mrB = Z2; }

        if (a >= R0 + 1) {
            int r = a - 1;                    // output row, in [0,255]
            u64 vLo = padd(padd(ma0.x, ma1.x), mrA.x);
            u64 vHi = padd(padd(ma0.y, ma1.y), mrA.y);
            u64 xLo = padd(padd(mb0.x, mb1.x), mrB.x);
            u64 xHi = padd(padd(mb0.y, mb1.y), mrB.y);
            float v1, v2, v3, v4, x1, x2, x3, x4;
            upk(v1, v2, vLo); upk(v3, v4, vHi);
            upk(x1, x2, xLo); upk(x3, x4, xHi);

            float L0  = __shfl_up_sync  (FULL, v4, 1);
            float Rr0 = __shfl_down_sync(FULL, v1, 1);
            float L1  = __shfl_up_sync  (FULL, x4, 1);
            float Rr1 = __shfl_down_sync(FULL, x1, 1);
            float S0  = __shfl_sync(FULL, v4, 31);
            float S1  = __shfl_sync(FULL, x1, 0);
            if (lane == 0)  { L0 = 0.f; L1 = S0; }
            if (lane == 31) { Rr0 = S1; Rr1 = 0.f; }

            ulonglong2 wgA = Wb[(r << 6) + qa], wgB = Wb[(r << 6) + qb];
            u64 v23 = pk(v2, v3);
            ulonglong2 oA;
            oA.x = pmul(padd(padd(pk(L0, v1), vLo), v23), wgA.x);
            oA.y = pmul(padd(padd(v23, vHi), pk(v4, Rr0)), wgA.y);
            och[(r << 6) + qa] = oA;
            u64 x23 = pk(x2, x3);
            ulonglong2 oB;
            oB.x = pmul(padd(padd(pk(L1, x1), xLo), x23), wgB.x);
            oB.y = pmul(padd(padd(x23, xHi), pk(x4, Rr1)), wgB.y);
            och[(r << 6) + qb] = oB;
        }

        // roll
        pa0 = pa1; pa1 = pa2; pb0 = pb1; pb1 = pb2;
        ma0 = ma1; ma1 = mrA; mb0 = mb1; mb1 = mrB;
    }
}

extern "C" void kernel_launch(void* const* d_in, const int* in_sizes, int n_in,
                              void* d_out, int out_size)
{
    const float* mask = (const float*)d_in[0];
    const float* edge = (const float*)d_in[1];
    // d_in[2] = iter_n is fixed at 2 by the problem setup; 2 iterations fused.
    (void)in_sizes; (void)n_in; (void)out_size;

    dim3 gp(HW / 32, HW / 32, NB);            // 8 x 8 x 8
    geg_prep<<<gp, 256>>>(edge);

    dim3 gs(HW / 16, NB * NC);                // 16 x 152 = 2432 CTAs
    geg_stencil<<<gs, 64>>>(mask, (float*)d_out);
}